// round 1
// baseline (speedup 1.0000x reference)
#include <cuda_runtime.h>
#include <cstdint>
#include <cstddef>

#define B_  4
#define T_  2048
#define C_  1024
#define H_  16
#define D_  64
#define M_  (B_ * T_)        // 8192
#define N3_ (3 * C_)         // 3072

// Scratch (static device globals — no allocation in kernel_launch)
__device__ __align__(16) float g_qkv[(size_t)M_ * N3_];   // [B*T, 3C]
__device__ __align__(16) float g_att[(size_t)M_ * C_];    // [B*T, C]

// ---------------------------------------------------------------------------
// SGEMM: C[M,N] = A[M,K] @ B[K,N], row-major, M%128==0, N%128==0, K%8==0
// 128x128 block tile, BK=8, 256 threads, 8x8 per thread (split 4+4 for
// conflict-free float4 shared reads).
// ---------------------------------------------------------------------------
__global__ __launch_bounds__(256, 2)
void sgemm128(const float* __restrict__ A, const float* __restrict__ Bm,
              float* __restrict__ Cm, int M, int N, int K) {
    __shared__ float As[8][128];   // [k][row]
    __shared__ float Bs[8][128];   // [k][col]

    const int tid = threadIdx.x;
    const int tx = tid & 15, ty = tid >> 4;
    const int rowBase = blockIdx.y << 7;
    const int colBase = blockIdx.x << 7;

    const int aRow = tid >> 1;             // 0..127
    const int aK4  = (tid & 1) << 2;       // 0 or 4
    const int bK   = tid >> 5;             // 0..7
    const int bC4  = (tid & 31) << 2;      // 0..124

    const float* Ap = A + (size_t)(rowBase + aRow) * K + aK4;
    const float* Bp = Bm + (size_t)bK * N + colBase + bC4;

    float acc[8][8];
#pragma unroll
    for (int i = 0; i < 8; i++)
#pragma unroll
        for (int j = 0; j < 8; j++) acc[i][j] = 0.f;

    for (int k0 = 0; k0 < K; k0 += 8) {
        float4 av = *(const float4*)Ap;
        float4 bv = *(const float4*)Bp;
        As[aK4 + 0][aRow] = av.x;
        As[aK4 + 1][aRow] = av.y;
        As[aK4 + 2][aRow] = av.z;
        As[aK4 + 3][aRow] = av.w;
        *(float4*)&Bs[bK][bC4] = bv;
        __syncthreads();

#pragma unroll
        for (int kk = 0; kk < 8; kk++) {
            float4 a0 = *(const float4*)&As[kk][ty * 4];
            float4 a1 = *(const float4*)&As[kk][64 + ty * 4];
            float4 b0 = *(const float4*)&Bs[kk][tx * 4];
            float4 b1 = *(const float4*)&Bs[kk][64 + tx * 4];
            float a[8] = {a0.x, a0.y, a0.z, a0.w, a1.x, a1.y, a1.z, a1.w};
            float b[8] = {b0.x, b0.y, b0.z, b0.w, b1.x, b1.y, b1.z, b1.w};
#pragma unroll
            for (int i = 0; i < 8; i++)
#pragma unroll
                for (int j = 0; j < 8; j++)
                    acc[i][j] = fmaf(a[i], b[j], acc[i][j]);
        }
        __syncthreads();
        Ap += 8;
        Bp += (size_t)8 * N;
    }

#pragma unroll
    for (int i = 0; i < 8; i++) {
        int r = rowBase + ((i < 4) ? (ty * 4 + i) : (64 + ty * 4 + (i - 4)));
        float4 c0v = make_float4(acc[i][0], acc[i][1], acc[i][2], acc[i][3]);
        float4 c1v = make_float4(acc[i][4], acc[i][5], acc[i][6], acc[i][7]);
        *(float4*)&Cm[(size_t)r * N + colBase + tx * 4] = c0v;
        *(float4*)&Cm[(size_t)r * N + colBase + 64 + tx * 4] = c1v;
    }
}

// ---------------------------------------------------------------------------
// Fused causal flash attention, fp32.
// One CTA = one (b, h, 64-query tile). 256 threads = 16x16; each thread owns a
// 4x4 tile of S/P and a 4x4 tile of O (rows ty*4.., cols tx*4..). Row softmax
// stats live in registers: each 16-lane half-warp exclusively owns rows
// ty*4..ty*4+3, reductions are shfl-only.
// qkv layout: [B*T, 3C]; head h: q at col h*64, k at C+h*64, v at 2C+h*64.
// ---------------------------------------------------------------------------
__global__ __launch_bounds__(256, 2)
void attn64(const float* __restrict__ qkv, float* __restrict__ att) {
    // Heavy q-tiles (most key tiles) first to reduce wave-tail imbalance.
    const int qt = (int)gridDim.x - 1 - (int)blockIdx.x;
    const int h  = blockIdx.y;
    const int b  = blockIdx.z;
    const int q0 = qt << 6;
    const int tid = threadIdx.x;
    const int tx = tid & 15, ty = tid >> 4;
    const int r0 = ty << 2, c0 = tx << 2;

    __shared__ float Qs[64][64];   // [r][d]   (reads are row-broadcast: pitch 64 OK)
    __shared__ float KP[64][64];   // K^T xor-swizzled: KP[d][c ^ (d&31)]; reused as P[r][c]
    __shared__ float Vs[64][64];   // [c][d]

    const float* base = qkv + (size_t)b * T_ * N3_ + (size_t)h * D_;
    const float* qb = base;
    const float* kb = base + C_;
    const float* vb = base + 2 * C_;

    // Load Q tile [64 x 64]
#pragma unroll
    for (int e = 0; e < 4; e++) {
        int idx4 = e * 256 + tid;          // 0..1023 float4 slots
        int r  = idx4 >> 4;
        int d4 = (idx4 & 15) << 2;
        float4 v = *(const float4*)&qb[(size_t)(q0 + r) * N3_ + d4];
        Qs[r][d4 + 0] = v.x; Qs[r][d4 + 1] = v.y;
        Qs[r][d4 + 2] = v.z; Qs[r][d4 + 3] = v.w;
    }

    float o[4][4];
    float mo[4], lo[4];
#pragma unroll
    for (int i = 0; i < 4; i++) {
        mo[i] = -1e30f;
        lo[i] = 0.f;
#pragma unroll
        for (int j = 0; j < 4; j++) o[i][j] = 0.f;
    }

    const float NEG_INF = __int_as_float(0xff800000u);
    const float scale = 0.125f;  // 1/sqrt(64)

    for (int jt = 0; jt <= qt; jt++) {
        const int k0 = jt << 6;
        // Previous tile's KP(P)/Vs fully consumed; Q store visible (1st iter).
        __syncthreads();

        // Load K (transposed + swizzled) and V tiles.
#pragma unroll
        for (int e = 0; e < 4; e++) {
            int idx4 = e * 256 + tid;
            int c  = idx4 >> 4;
            int d4 = (idx4 & 15) << 2;
            float4 kv = *(const float4*)&kb[(size_t)(k0 + c) * N3_ + d4];
            KP[d4 + 0][c ^ ((d4 + 0) & 31)] = kv.x;
            KP[d4 + 1][c ^ ((d4 + 1) & 31)] = kv.y;
            KP[d4 + 2][c ^ ((d4 + 2) & 31)] = kv.z;
            KP[d4 + 3][c ^ ((d4 + 3) & 31)] = kv.w;
            float4 vv = *(const float4*)&vb[(size_t)(k0 + c) * N3_ + d4];
            *(float4*)&Vs[c][d4] = vv;
        }
        __syncthreads();

        // S = Q @ K^T  (4x4 per thread)
        float s[4][4];
#pragma unroll
        for (int i = 0; i < 4; i++)
#pragma unroll
            for (int j = 0; j < 4; j++) s[i][j] = 0.f;

#pragma unroll 8
        for (int d = 0; d < 64; d++) {
            float a0 = Qs[r0 + 0][d];
            float a1 = Qs[r0 + 1][d];
            float a2 = Qs[r0 + 2][d];
            float a3 = Qs[r0 + 3][d];
            const int m = d & 31;
            float b0 = KP[d][(c0 + 0) ^ m];
            float b1 = KP[d][(c0 + 1) ^ m];
            float b2 = KP[d][(c0 + 2) ^ m];
            float b3 = KP[d][(c0 + 3) ^ m];
            s[0][0] = fmaf(a0, b0, s[0][0]); s[0][1] = fmaf(a0, b1, s[0][1]);
            s[0][2] = fmaf(a0, b2, s[0][2]); s[0][3] = fmaf(a0, b3, s[0][3]);
            s[1][0] = fmaf(a1, b0, s[1][0]); s[1][1] = fmaf(a1, b1, s[1][1]);
            s[1][2] = fmaf(a1, b2, s[1][2]); s[1][3] = fmaf(a1, b3, s[1][3]);
            s[2][0] = fmaf(a2, b0, s[2][0]); s[2][1] = fmaf(a2, b1, s[2][1]);
            s[2][2] = fmaf(a2, b2, s[2][2]); s[2][3] = fmaf(a2, b3, s[2][3]);
            s[3][0] = fmaf(a3, b0, s[3][0]); s[3][1] = fmaf(a3, b1, s[3][1]);
            s[3][2] = fmaf(a3, b2, s[3][2]); s[3][3] = fmaf(a3, b3, s[3][3]);
        }

        // Scale + causal mask (only the diagonal tile needs masking).
        const bool diag = (jt == qt);
        float rm[4];
#pragma unroll
        for (int i = 0; i < 4; i++) {
#pragma unroll
            for (int j = 0; j < 4; j++) {
                float v = s[i][j] * scale;
                if (diag && (c0 + j > r0 + i)) v = NEG_INF;
                s[i][j] = v;
            }
            rm[i] = fmaxf(fmaxf(s[i][0], s[i][1]), fmaxf(s[i][2], s[i][3]));
        }
        // Row-max across the 16 lanes (tx) of this half-warp.
#pragma unroll
        for (int off = 1; off < 16; off <<= 1) {
#pragma unroll
            for (int i = 0; i < 4; i++)
                rm[i] = fmaxf(rm[i], __shfl_xor_sync(0xffffffffu, rm[i], off));
        }

        float sc[4], rs[4];
#pragma unroll
        for (int i = 0; i < 4; i++) {
            float mn = fmaxf(mo[i], rm[i]);
            sc[i] = __expf(mo[i] - mn);
            mo[i] = mn;
            rs[i] = 0.f;
#pragma unroll
            for (int j = 0; j < 4; j++) {
                float p = __expf(s[i][j] - mn);
                s[i][j] = p;
                rs[i] += p;
            }
        }
#pragma unroll
        for (int off = 1; off < 16; off <<= 1) {
#pragma unroll
            for (int i = 0; i < 4; i++)
                rs[i] += __shfl_xor_sync(0xffffffffu, rs[i], off);
        }
#pragma unroll
        for (int i = 0; i < 4; i++) {
            lo[i] = lo[i] * sc[i] + rs[i];
#pragma unroll
            for (int j = 0; j < 4; j++) o[i][j] *= sc[i];
        }

        // All warps must be done reading KP-as-K before overwriting with P.
        __syncthreads();
#pragma unroll
        for (int i = 0; i < 4; i++)
#pragma unroll
            for (int j = 0; j < 4; j++)
                KP[r0 + i][c0 + j] = s[i][j];
        // PV only reads rows r0..r0+3, written entirely by this half-warp.
        __syncwarp();

        // O += P @ V
#pragma unroll 8
        for (int j = 0; j < 64; j++) {
            float p0 = KP[r0 + 0][j];
            float p1 = KP[r0 + 1][j];
            float p2 = KP[r0 + 2][j];
            float p3 = KP[r0 + 3][j];
            float v0 = Vs[j][c0 + 0];
            float v1 = Vs[j][c0 + 1];
            float v2 = Vs[j][c0 + 2];
            float v3 = Vs[j][c0 + 3];
            o[0][0] = fmaf(p0, v0, o[0][0]); o[0][1] = fmaf(p0, v1, o[0][1]);
            o[0][2] = fmaf(p0, v2, o[0][2]); o[0][3] = fmaf(p0, v3, o[0][3]);
            o[1][0] = fmaf(p1, v0, o[1][0]); o[1][1] = fmaf(p1, v1, o[1][1]);
            o[1][2] = fmaf(p1, v2, o[1][2]); o[1][3] = fmaf(p1, v3, o[1][3]);
            o[2][0] = fmaf(p2, v0, o[2][0]); o[2][1] = fmaf(p2, v1, o[2][1]);
            o[2][2] = fmaf(p2, v2, o[2][2]); o[2][3] = fmaf(p2, v3, o[2][3]);
            o[3][0] = fmaf(p3, v0, o[3][0]); o[3][1] = fmaf(p3, v1, o[3][1]);
            o[3][2] = fmaf(p3, v2, o[3][2]); o[3][3] = fmaf(p3, v3, o[3][3]);
        }
    }

    // Epilogue: normalize and write [B,T,C] (head h at columns h*64).
    float* ob = att + ((size_t)(b * T_) + q0) * C_ + (size_t)h * D_;
#pragma unroll
    for (int i = 0; i < 4; i++) {
        float inv = 1.f / lo[i];
        float4 v = make_float4(o[i][0] * inv, o[i][1] * inv,
                               o[i][2] * inv, o[i][3] * inv);
        *(float4*)&ob[(size_t)(r0 + i) * C_ + c0] = v;
    }
}

// ---------------------------------------------------------------------------
// Launch: x @ w_qkv -> g_qkv ; attention -> g_att ; g_att @ w_proj -> out
// ---------------------------------------------------------------------------
extern "C" void kernel_launch(void* const* d_in, const int* in_sizes, int n_in,
                              void* d_out, int out_size) {
    const float* x      = (const float*)d_in[0];
    const float* w_qkv  = (const float*)d_in[1];
    const float* w_proj = (const float*)d_in[2];
    float* out = (float*)d_out;

    void* qkv_p = nullptr;
    void* att_p = nullptr;
    cudaGetSymbolAddress(&qkv_p, g_qkv);
    cudaGetSymbolAddress(&att_p, g_att);
    float* qkv = (float*)qkv_p;
    float* att = (float*)att_p;

    sgemm128<<<dim3(N3_ / 128, M_ / 128), 256>>>(x, w_qkv, qkv, M_, N3_, C_);
    attn64<<<dim3(T_ / 64, H_, B_), 256>>>(qkv, att);
    sgemm128<<<dim3(C_ / 128, M_ / 128), 256>>>(att, w_proj, out, M_, C_, C_);
}